// round 2
// baseline (speedup 1.0000x reference)
#include <cuda_runtime.h>
#include <math.h>

// 1/sqrt(1 + 1e-3)
#define ISRC 0.9995003746877732f
#define XS 65   // padded row stride of x in smem (bank-conflict-free column reads)

// scratch (static __device__ arrays: allocation-free)
__device__ float g_x[64 * 32768];        // GNN output, (B, N*64) row-major
__device__ float g_part[128 * 64 * 128]; // split-K partials: (kchunk, b, d)

// ----------------------------------------------------------------------------
// GNN layer: pairwise S/T + fused GEMM + bias/mask/BN/tanh, all in smem.
//   y[i,o] = sum_k x[i,k]*A[k,o]  +  (m_i*S_i - 1) * sum_k x[i,k]*A[F+k,o]
//            + (m_i*T_i)*A[2F,o] + b[o],   then *m_i, BN, tanh
// ----------------------------------------------------------------------------
template <int F, int ND>
__device__ __forceinline__ void do_layer(
    float* x_s, float* A_s, float* c_s, float* s_s, float* t_s, float* m_s,
    float* cn_s,
    const float* __restrict__ A, const float* __restrict__ bias,
    const float* __restrict__ bng, const float* __restrict__ bnb)
{
    const int tid = threadIdx.x;
    constexpr int KT = 2 * F + 1;

    __syncthreads();  // previous layer fully done (x_s final, A_s/cn_s reads done)

    // stage layer weights + per-column constants
    for (int idx = tid; idx < KT * 64; idx += 512) A_s[idx] = A[idx];
    if (tid < 64) {
        cn_s[tid]        = bias[tid];
        cn_s[64 + tid]   = bng[tid] * ISRC;
        cn_s[128 + tid]  = bnb[tid];
    }
    // c = last ND features of own row (pad to 4 with zeros)
    {
        const float* xr = x_s + tid * XS;
        float4 cv;
        cv.x = xr[F - ND + 0];
        cv.y = xr[F - ND + 1];
        cv.z = (ND == 4) ? xr[F - 2] : 0.f;
        cv.w = (ND == 4) ? xr[F - 1] : 0.f;
        reinterpret_cast<float4*>(c_s)[tid] = cv;
    }
    __syncthreads();

    // pairwise sums: thread i loops all j (broadcast LDS.128)
    {
        const float4 ci = reinterpret_cast<const float4*>(c_s)[tid];
        float S = 0.f, T = 0.f;
#pragma unroll 8
        for (int j = 0; j < 512; j++) {
            float4 cj = reinterpret_cast<const float4*>(c_s)[j];
            float dx = cj.x - ci.x;
            float dy = cj.y - ci.y;
            float d = dx * dx + dy * dy;
            if (ND == 4) {
                float dz = cj.z - ci.z;
                float dw = cj.w - ci.w;
                d += dz * dz + dw * dw;
            }
            float w = __expf(-10.f * d);
            S += w;
            T = fmaf(d, w, T);
        }
        float m = m_s[tid];
        s_s[tid] = fmaf(m, S, -1.f);  // (m*S - 1)
        t_s[tid] = m * T;
    }
    __syncthreads();

    // GEMM: 512 threads, 2 row-halves of 256; each thread 4 rows x 8 cols,
    // dual accumulators (u for A_top, v for A_mid; v scaled by s_i at the end).
    const int cs0   = (tid & 7) * 8;
    const int rslot = tid >> 3;  // 0..63
#pragma unroll 1
    for (int half = 0; half < 2; half++) {
        const int r0 = half * 256 + rslot * 4;
        float u[4][8], v[4][8];
#pragma unroll
        for (int r = 0; r < 4; r++)
#pragma unroll
            for (int c = 0; c < 8; c++) { u[r][c] = 0.f; v[r][c] = 0.f; }

        const float* xp0 = x_s + (r0 + 0) * XS;
        const float* xp1 = x_s + (r0 + 1) * XS;
        const float* xp2 = x_s + (r0 + 2) * XS;
        const float* xp3 = x_s + (r0 + 3) * XS;
#pragma unroll 4
        for (int k = 0; k < F; k++) {
            float4 a0 = *reinterpret_cast<const float4*>(&A_s[k * 64 + cs0]);
            float4 a1 = *reinterpret_cast<const float4*>(&A_s[k * 64 + cs0 + 4]);
            float4 q0 = *reinterpret_cast<const float4*>(&A_s[(F + k) * 64 + cs0]);
            float4 q1 = *reinterpret_cast<const float4*>(&A_s[(F + k) * 64 + cs0 + 4]);
            float xv[4];
            xv[0] = xp0[k]; xv[1] = xp1[k]; xv[2] = xp2[k]; xv[3] = xp3[k];
#pragma unroll
            for (int r = 0; r < 4; r++) {
                u[r][0] = fmaf(xv[r], a0.x, u[r][0]);
                u[r][1] = fmaf(xv[r], a0.y, u[r][1]);
                u[r][2] = fmaf(xv[r], a0.z, u[r][2]);
                u[r][3] = fmaf(xv[r], a0.w, u[r][3]);
                u[r][4] = fmaf(xv[r], a1.x, u[r][4]);
                u[r][5] = fmaf(xv[r], a1.y, u[r][5]);
                u[r][6] = fmaf(xv[r], a1.z, u[r][6]);
                u[r][7] = fmaf(xv[r], a1.w, u[r][7]);
                v[r][0] = fmaf(xv[r], q0.x, v[r][0]);
                v[r][1] = fmaf(xv[r], q0.y, v[r][1]);
                v[r][2] = fmaf(xv[r], q0.z, v[r][2]);
                v[r][3] = fmaf(xv[r], q0.w, v[r][3]);
                v[r][4] = fmaf(xv[r], q1.x, v[r][4]);
                v[r][5] = fmaf(xv[r], q1.y, v[r][5]);
                v[r][6] = fmaf(xv[r], q1.z, v[r][6]);
                v[r][7] = fmaf(xv[r], q1.w, v[r][7]);
            }
        }
        __syncthreads();  // all reads of this half's rows done before overwrite
#pragma unroll
        for (int r = 0; r < 4; r++) {
            const int i = r0 + r;
            const float s = s_s[i], t = t_s[i], m = m_s[i];
#pragma unroll
            for (int c = 0; c < 8; c++) {
                float y = fmaf(s, v[r][c], u[r][c]);
                y = fmaf(t, A_s[2 * F * 64 + cs0 + c], y);
                y += cn_s[cs0 + c];
                y *= m;
                x_s[i * XS + cs0 + c] =
                    tanhf(fmaf(cn_s[64 + cs0 + c], y, cn_s[128 + cs0 + c]));
            }
        }
        // next half reads disjoint rows -> no barrier needed here
    }
}

// ----------------------------------------------------------------------------
__global__ __launch_bounds__(512, 1) void gnn_kernel(
    const float* __restrict__ xx,
    const float* __restrict__ e1, const float* __restrict__ e2,
    const float* __restrict__ e3,
    const float* __restrict__ A0, const float* __restrict__ b0,
    const float* __restrict__ Ar, const float* __restrict__ br,
    const float* __restrict__ bng, const float* __restrict__ bnb)
{
    extern __shared__ float sm[];
    float* x_s  = sm;                  // 512*65
    float* A_s  = x_s + 512 * XS;      // 129*64
    float* c_s  = A_s + 129 * 64;      // 512*4
    float* s_s  = c_s + 512 * 4;       // 512
    float* t_s  = s_s + 512;           // 512
    float* m_s  = t_s + 512;           // 512
    float* cn_s = m_s + 512;           // 192

    const int b   = blockIdx.x;
    const int tid = threadIdx.x;

    // build initial 33 features for own row
    {
        const float* row = xx + ((size_t)b * 512 + tid) * 30;
        float m = row[0];
        m_s[tid] = m;
        int i1 = (int)fabsf(row[27]);
        int i2 = (int)fabsf(row[28]);
        int i3 = (int)fabsf(row[29]);
        float* xr = x_s + tid * XS;
        xr[0] = e1[2 * i1];     xr[1] = e1[2 * i1 + 1];
        xr[2] = e2[2 * i2];     xr[3] = e2[2 * i2 + 1];
        xr[4] = e3[2 * i3];     xr[5] = e3[2 * i3 + 1];
#pragma unroll
        for (int k = 0; k < 27; k++) xr[6 + k] = row[k];
    }

    do_layer<33, 2>(x_s, A_s, c_s, s_s, t_s, m_s, cn_s, A0, b0, bng, bnb);
#pragma unroll 1
    for (int l = 0; l < 4; l++) {
        do_layer<64, 4>(x_s, A_s, c_s, s_s, t_s, m_s, cn_s,
                        Ar + l * 129 * 64, br + l * 64,
                        bng + (l + 1) * 64, bnb + (l + 1) * 64);
    }
    __syncthreads();
    float* out = g_x + (size_t)b * 32768;
    for (int idx = tid; idx < 32768; idx += 512)
        out[idx] = x_s[(idx >> 6) * XS + (idx & 63)];
}

// ----------------------------------------------------------------------------
// Dense layer 0 split-K: 128 CTAs, each owns a K-chunk of 256.
// Deterministic: partials stored, reduced in finalize (no float atomics).
// ----------------------------------------------------------------------------
__global__ __launch_bounds__(256, 1) void dense0_kernel(const float* __restrict__ W)
{
    extern __shared__ float sm[];
    float* Xs = sm;              // 64 x 256
    float* Ws = Xs + 64 * 256;   // 256 x 128
    const int tid = threadIdx.x;
    const int kc  = blockIdx.x;

    for (int idx = tid; idx < 64 * 256; idx += 256) {
        int b = idx >> 8, k = idx & 255;
        Xs[idx] = g_x[(size_t)b * 32768 + kc * 256 + k];
    }
    const float* wsrc = W + (size_t)kc * 256 * 128;
    for (int idx = tid; idx < 256 * 128; idx += 256) Ws[idx] = wsrc[idx];
    __syncthreads();

    const int bs = tid >> 5;   // 0..7  -> rows b = bs*8..bs*8+7
    const int ds = tid & 31;   // 0..31 -> cols d = ds*4..ds*4+3
    float acc[8][4];
#pragma unroll
    for (int r = 0; r < 8; r++)
#pragma unroll
        for (int j = 0; j < 4; j++) acc[r][j] = 0.f;

#pragma unroll 4
    for (int k = 0; k < 256; k++) {
        float4 w4 = *reinterpret_cast<const float4*>(&Ws[k * 128 + ds * 4]);
#pragma unroll
        for (int r = 0; r < 8; r++) {
            float xv = Xs[(bs * 8 + r) * 256 + k];  // warp-broadcast
            acc[r][0] = fmaf(xv, w4.x, acc[r][0]);
            acc[r][1] = fmaf(xv, w4.y, acc[r][1]);
            acc[r][2] = fmaf(xv, w4.z, acc[r][2]);
            acc[r][3] = fmaf(xv, w4.w, acc[r][3]);
        }
    }
    float* dst = g_part + (size_t)kc * 8192;
#pragma unroll
    for (int r = 0; r < 8; r++)
#pragma unroll
        for (int j = 0; j < 4; j++)
            dst[(bs * 8 + r) * 128 + ds * 4 + j] = acc[r][j];
}

// ----------------------------------------------------------------------------
// Finalize: reduce partials, BN+sigmoid, dense1, BN+sigmoid, W2, write (64,4)
// ----------------------------------------------------------------------------
__global__ __launch_bounds__(128, 1) void finalize_kernel(
    const float* __restrict__ db0, const float* __restrict__ dW1,
    const float* __restrict__ db1, const float* __restrict__ dbng,
    const float* __restrict__ dbnb, const float* __restrict__ W2,
    const float* __restrict__ b2, float* __restrict__ out)
{
    __shared__ float h0[128];
    __shared__ float h1[128];
    const int b = blockIdx.x;
    const int d = threadIdx.x;

    float a = db0[d];
#pragma unroll 4
    for (int kc = 0; kc < 128; kc++) a += g_part[(size_t)kc * 8192 + b * 128 + d];
    a = fmaf(dbng[d] * ISRC, a, dbnb[d]);
    h0[d] = 1.f / (1.f + __expf(-a));
    __syncthreads();

    float s = 0.f;
#pragma unroll 8
    for (int k = 0; k < 128; k++) s = fmaf(h0[k], dW1[k * 128 + d], s);
    s += db1[d];
    s = fmaf(dbng[128 + d] * ISRC, s, dbnb[128 + d]);
    h1[d] = 1.f / (1.f + __expf(-s));
    __syncthreads();

    if (d < 4) {
        float o = 0.f;
        if (d < 2) {
            o = b2[d];
            for (int k = 0; k < 128; k++) o = fmaf(h1[k], W2[k * 2 + d], o);
        }
        out[b * 4 + d] = o;
    }
}

// ----------------------------------------------------------------------------
extern "C" void kernel_launch(void* const* d_in, const int* in_sizes, int n_in,
                              void* d_out, int out_size)
{
    const float* xx   = (const float*)d_in[0];
    const float* emb1 = (const float*)d_in[1];
    const float* emb2 = (const float*)d_in[2];
    const float* emb3 = (const float*)d_in[3];
    const float* A0   = (const float*)d_in[4];
    const float* b0   = (const float*)d_in[5];
    const float* Ar   = (const float*)d_in[6];
    const float* br   = (const float*)d_in[7];
    const float* bng  = (const float*)d_in[8];
    const float* bnb  = (const float*)d_in[9];
    const float* dW0  = (const float*)d_in[10];
    const float* db0  = (const float*)d_in[11];
    const float* dW1  = (const float*)d_in[12];
    const float* db1  = (const float*)d_in[13];
    const float* dbng = (const float*)d_in[14];
    const float* dbnb = (const float*)d_in[15];
    const float* W2   = (const float*)d_in[16];
    const float* b2   = (const float*)d_in[17];
    float* out = (float*)d_out;

    const int GNN_SMEM = (512 * XS + 129 * 64 + 512 * 4 + 512 * 3 + 192) * 4; // 181248
    const int D0_SMEM  = (64 * 256 + 256 * 128) * 4;                          // 196608

    cudaFuncSetAttribute(gnn_kernel, cudaFuncAttributeMaxDynamicSharedMemorySize,
                         GNN_SMEM);
    cudaFuncSetAttribute(dense0_kernel, cudaFuncAttributeMaxDynamicSharedMemorySize,
                         D0_SMEM);

    gnn_kernel<<<64, 512, GNN_SMEM>>>(xx, emb1, emb2, emb3, A0, b0, Ar, br, bng, bnb);
    dense0_kernel<<<128, 256, D0_SMEM>>>(dW0);
    finalize_kernel<<<64, 128>>>(db0, dW1, db1, dbng, dbnb, W2, b2, out);
}

// round 3
// speedup vs baseline: 1.6087x; 1.6087x over previous
#include <cuda_runtime.h>
#include <math.h>

// 1/sqrt(1 + 1e-3)
#define ISRC 0.9995003746877732f
#define XS 65   // padded row stride of x in smem (bank-conflict-free column reads)

typedef unsigned long long ull;

// scratch (static __device__ arrays: allocation-free)
__device__ float g_x0[64 * 32768];       // ping
__device__ float g_x1[64 * 32768];       // pong
__device__ float g_part[128 * 64 * 128]; // split-K partials: (kchunk, b, d)

// ---------------- f32x2 helpers (Blackwell packed fp32) ----------------
__device__ __forceinline__ ull pk2(float a, float b) {
    ull r; asm("mov.b64 %0,{%1,%2};" : "=l"(r) : "f"(a), "f"(b)); return r;
}
__device__ __forceinline__ void up2(ull p, float& a, float& b) {
    asm("mov.b64 {%0,%1},%2;" : "=f"(a), "=f"(b) : "l"(p));
}
__device__ __forceinline__ ull add2(ull a, ull b) {
    ull r; asm("add.rn.f32x2 %0,%1,%2;" : "=l"(r) : "l"(a), "l"(b)); return r;
}
__device__ __forceinline__ ull mul2(ull a, ull b) {
    ull r; asm("mul.rn.f32x2 %0,%1,%2;" : "=l"(r) : "l"(a), "l"(b)); return r;
}
__device__ __forceinline__ ull fma2_(ull a, ull b, ull c) {
    ull r; asm("fma.rn.f32x2 %0,%1,%2,%3;" : "=l"(r) : "l"(a), "l"(b), "l"(c));
    return r;
}

// ----------------------------------------------------------------------------
// One GNN layer, 2 CTAs per batch (each owns 256 rows). x ping-pongs through
// global memory (stays L2-resident). c (last ND feats of all 512 rows) is read
// directly from the previous layer's global x / from xx for the first layer.
//   y[i,o] = sum_k x[i,k]*A[k,o] + (m_i*S_i-1)*sum_k x[i,k]*A[F+k,o]
//            + (m_i*T_i)*A[2F,o] + b[o],  then *m_i, BN, tanh
// ----------------------------------------------------------------------------
template <int F, int ND, bool FIRST>
__global__ __launch_bounds__(512, 1) void layer_kernel(
    const float* __restrict__ xx,
    const float* __restrict__ e1, const float* __restrict__ e2,
    const float* __restrict__ e3,
    const float* __restrict__ A, const float* __restrict__ bias,
    const float* __restrict__ bng, const float* __restrict__ bnb,
    const float* __restrict__ xin, float* __restrict__ xout)
{
    extern __shared__ float sm[];
    float* c_s  = sm;                 // 512*4 (16B aligned at base)
    float* x_s  = c_s + 2048;         // 256*XS
    float* A_s  = x_s + 256 * XS;     // up to 129*64
    float* m_s  = A_s + 129 * 64;     // 256
    float* s_s  = m_s + 256;          // 256
    float* t_s  = s_s + 256;          // 256
    float* sp   = t_s + 256;          // 512
    float* tp   = sp + 512;           // 512
    float* cn_s = tp + 512;           // 192

    const int b   = blockIdx.y;
    const int h   = blockIdx.x;       // row half: rows [h*256, h*256+256)
    const int tid = threadIdx.x;
    constexpr int KT = 2 * F + 1;

    // ---- stage weights / constants ----
    for (int idx = tid; idx < KT * 64; idx += 512) A_s[idx] = A[idx];
    if (tid < 64) {
        cn_s[tid]       = bias[tid];
        cn_s[64 + tid]  = bng[tid] * ISRC;
        cn_s[128 + tid] = bnb[tid];
    }
    if (tid < 256)
        m_s[tid] = xx[((size_t)b * 512 + h * 256 + tid) * 30];

    if (FIRST) {
        // c for ALL 512 rows comes straight from xx cols 25,26 (== x[31],x[32])
        const float* row = xx + ((size_t)b * 512 + tid) * 30;
        float4 cv; cv.x = row[25]; cv.y = row[26]; cv.z = 0.f; cv.w = 0.f;
        reinterpret_cast<float4*>(c_s)[tid] = cv;
        // build own 256 rows of 33 features
        if (tid < 256) {
            const float* r = xx + ((size_t)b * 512 + h * 256 + tid) * 30;
            int i1 = (int)fabsf(r[27]);
            int i2 = (int)fabsf(r[28]);
            int i3 = (int)fabsf(r[29]);
            float* xr = x_s + tid * XS;
            xr[0] = e1[2 * i1]; xr[1] = e1[2 * i1 + 1];
            xr[2] = e2[2 * i2]; xr[3] = e2[2 * i2 + 1];
            xr[4] = e3[2 * i3]; xr[5] = e3[2 * i3 + 1];
#pragma unroll
            for (int k = 0; k < 27; k++) xr[6 + k] = r[k];
        }
    } else {
        // c for all 512 rows: last 4 feats (cols 60..63, 16B aligned)
        {
            const float* src = xin + ((size_t)b * 512 + tid) * 64;
            reinterpret_cast<float4*>(c_s)[tid] =
                *reinterpret_cast<const float4*>(src + 60);
        }
        // own 256 rows of x (vector global loads, scalar smem stores)
        for (int idx = tid; idx < 4096; idx += 512) {
            int r = idx >> 4, cq = (idx & 15) * 4;
            float4 v = *reinterpret_cast<const float4*>(
                xin + ((size_t)b * 512 + h * 256 + r) * 64 + cq);
            float* d = x_s + r * XS + cq;
            d[0] = v.x; d[1] = v.y; d[2] = v.z; d[3] = v.w;
        }
    }
    __syncthreads();

    // ---- pairwise S/T: thread (i = tid&255) handles j-half (tid>>8) ----
    {
        const int i  = tid & 255;
        const int jh = tid >> 8;
        const float4 ci = reinterpret_cast<const float4*>(c_s)[h * 256 + i];
        const ull ni01 = pk2(-ci.x, -ci.y);
        const ull ni23 = pk2(-ci.z, -ci.w);
        const ulonglong2* cp = reinterpret_cast<const ulonglong2*>(c_s);
        float S = 0.f, T = 0.f;
#pragma unroll 8
        for (int j = jh * 256; j < jh * 256 + 256; j++) {
            ulonglong2 cj = cp[j];
            ull dxy = add2(cj.x, ni01);
            ull q = mul2(dxy, dxy);
            if (ND == 4) {
                ull dzw = add2(cj.y, ni23);
                q = fma2_(dzw, dzw, q);
            }
            float qlo, qhi; up2(q, qlo, qhi);
            float d = qlo + qhi;
            float w = __expf(-10.f * d);
            S += w;
            T = fmaf(d, w, T);
        }
        sp[tid] = S; tp[tid] = T;
    }
    __syncthreads();
    if (tid < 256) {
        float S = sp[tid] + sp[tid + 256];
        float T = tp[tid] + tp[tid + 256];
        float m = m_s[tid];
        s_s[tid] = fmaf(m, S, -1.f);   // (m*S - 1)
        t_s[tid] = m * T;
    }
    __syncthreads();

    // ---- GEMM: each thread 4 rows x 8 cols, packed f32x2 FMAs ----
    const int cs0 = (tid & 7) * 8;
    const int r0  = (tid >> 3) * 4;    // local rows r0..r0+3
    ull u[4][4], v[4][4];
#pragma unroll
    for (int r = 0; r < 4; r++)
#pragma unroll
        for (int c = 0; c < 4; c++) { u[r][c] = 0ull; v[r][c] = 0ull; }

    const float* xr0 = x_s + (r0 + 0) * XS;
    const float* xr1 = x_s + (r0 + 1) * XS;
    const float* xr2 = x_s + (r0 + 2) * XS;
    const float* xr3 = x_s + (r0 + 3) * XS;

#pragma unroll 4
    for (int k = 0; k < F; k++) {
        ulonglong2 a01 = *reinterpret_cast<const ulonglong2*>(&A_s[k * 64 + cs0]);
        ulonglong2 a23 = *reinterpret_cast<const ulonglong2*>(&A_s[k * 64 + cs0 + 4]);
        ulonglong2 q01 = *reinterpret_cast<const ulonglong2*>(&A_s[(F + k) * 64 + cs0]);
        ulonglong2 q23 = *reinterpret_cast<const ulonglong2*>(&A_s[(F + k) * 64 + cs0 + 4]);
        ull xp[4];
        { float xv = xr0[k]; xp[0] = pk2(xv, xv); }
        { float xv = xr1[k]; xp[1] = pk2(xv, xv); }
        { float xv = xr2[k]; xp[2] = pk2(xv, xv); }
        { float xv = xr3[k]; xp[3] = pk2(xv, xv); }
#pragma unroll
        for (int r = 0; r < 4; r++) {
            u[r][0] = fma2_(xp[r], a01.x, u[r][0]);
            u[r][1] = fma2_(xp[r], a01.y, u[r][1]);
            u[r][2] = fma2_(xp[r], a23.x, u[r][2]);
            u[r][3] = fma2_(xp[r], a23.y, u[r][3]);
            v[r][0] = fma2_(xp[r], q01.x, v[r][0]);
            v[r][1] = fma2_(xp[r], q01.y, v[r][1]);
            v[r][2] = fma2_(xp[r], q23.x, v[r][2]);
            v[r][3] = fma2_(xp[r], q23.y, v[r][3]);
        }
    }

    // ---- epilogue: combine, bias, mask, BN, tanh, store to global ----
#pragma unroll
    for (int r = 0; r < 4; r++) {
        const int i = r0 + r;
        const float s = s_s[i], t = t_s[i], m = m_s[i];
        const ull s2 = pk2(s, s);
        float o[8];
#pragma unroll
        for (int cp2 = 0; cp2 < 4; cp2++) {
            ull y2 = fma2_(s2, v[r][cp2], u[r][cp2]);
            float ylo, yhi; up2(y2, ylo, yhi);
            const int c = cs0 + cp2 * 2;
            float a0 = fmaf(t, A_s[2 * F * 64 + c], ylo) + cn_s[c];
            float a1 = fmaf(t, A_s[2 * F * 64 + c + 1], yhi) + cn_s[c + 1];
            a0 *= m; a1 *= m;
            o[cp2 * 2]     = tanhf(fmaf(cn_s[64 + c], a0, cn_s[128 + c]));
            o[cp2 * 2 + 1] = tanhf(fmaf(cn_s[64 + c + 1], a1, cn_s[128 + c + 1]));
        }
        float4* dst = reinterpret_cast<float4*>(
            xout + ((size_t)b * 512 + h * 256 + i) * 64 + cs0);
        dst[0] = make_float4(o[0], o[1], o[2], o[3]);
        dst[1] = make_float4(o[4], o[5], o[6], o[7]);
    }
}

// ----------------------------------------------------------------------------
// Dense layer 0 split-K: 128 CTAs, each owns a K-chunk of 256.
// Deterministic: partials stored, reduced in finalize (no float atomics).
// ----------------------------------------------------------------------------
__global__ __launch_bounds__(256, 1) void dense0_kernel(const float* __restrict__ W)
{
    extern __shared__ float sm[];
    float* Xs = sm;              // 64 x 256
    float* Ws = Xs + 64 * 256;   // 256 x 128
    const int tid = threadIdx.x;
    const int kc  = blockIdx.x;

    for (int idx = tid; idx < 64 * 256; idx += 256) {
        int b = idx >> 8, k = idx & 255;
        Xs[idx] = g_x0[(size_t)b * 32768 + kc * 256 + k];
    }
    const float* wsrc = W + (size_t)kc * 256 * 128;
    for (int idx = tid; idx < 256 * 128; idx += 256) Ws[idx] = wsrc[idx];
    __syncthreads();

    const int bs = tid >> 5;   // 0..7  -> rows b = bs*8..bs*8+7
    const int ds = tid & 31;   // 0..31 -> cols d = ds*4..ds*4+3
    float acc[8][4];
#pragma unroll
    for (int r = 0; r < 8; r++)
#pragma unroll
        for (int j = 0; j < 4; j++) acc[r][j] = 0.f;

#pragma unroll 4
    for (int k = 0; k < 256; k++) {
        float4 w4 = *reinterpret_cast<const float4*>(&Ws[k * 128 + ds * 4]);
#pragma unroll
        for (int r = 0; r < 8; r++) {
            float xv = Xs[(bs * 8 + r) * 256 + k];  // warp-broadcast
            acc[r][0] = fmaf(xv, w4.x, acc[r][0]);
            acc[r][1] = fmaf(xv, w4.y, acc[r][1]);
            acc[r][2] = fmaf(xv, w4.z, acc[r][2]);
            acc[r][3] = fmaf(xv, w4.w, acc[r][3]);
        }
    }
    float* dst = g_part + (size_t)kc * 8192;
#pragma unroll
    for (int r = 0; r < 8; r++)
#pragma unroll
        for (int j = 0; j < 4; j++)
            dst[(bs * 8 + r) * 128 + ds * 4 + j] = acc[r][j];
}

// ----------------------------------------------------------------------------
// Finalize: reduce partials, BN+sigmoid, dense1, BN+sigmoid, W2, write (64,4)
// ----------------------------------------------------------------------------
__global__ __launch_bounds__(128, 1) void finalize_kernel(
    const float* __restrict__ db0, const float* __restrict__ dW1,
    const float* __restrict__ db1, const float* __restrict__ dbng,
    const float* __restrict__ dbnb, const float* __restrict__ W2,
    const float* __restrict__ b2, float* __restrict__ out)
{
    __shared__ float h0[128];
    __shared__ float h1[128];
    const int b = blockIdx.x;
    const int d = threadIdx.x;

    float a = db0[d];
#pragma unroll 4
    for (int kc = 0; kc < 128; kc++) a += g_part[(size_t)kc * 8192 + b * 128 + d];
    a = fmaf(dbng[d] * ISRC, a, dbnb[d]);
    h0[d] = 1.f / (1.f + __expf(-a));
    __syncthreads();

    float s = 0.f;
#pragma unroll 8
    for (int k = 0; k < 128; k++) s = fmaf(h0[k], dW1[k * 128 + d], s);
    s += db1[d];
    s = fmaf(dbng[128 + d] * ISRC, s, dbnb[128 + d]);
    h1[d] = 1.f / (1.f + __expf(-s));
    __syncthreads();

    if (d < 4) {
        float o = 0.f;
        if (d < 2) {
            o = b2[d];
            for (int k = 0; k < 128; k++) o = fmaf(h1[k], W2[k * 2 + d], o);
        }
        out[b * 4 + d] = o;
    }
}

// ----------------------------------------------------------------------------
extern "C" void kernel_launch(void* const* d_in, const int* in_sizes, int n_in,
                              void* d_out, int out_size)
{
    const float* xx   = (const float*)d_in[0];
    const float* emb1 = (const float*)d_in[1];
    const float* emb2 = (const float*)d_in[2];
    const float* emb3 = (const float*)d_in[3];
    const float* A0   = (const float*)d_in[4];
    const float* b0   = (const float*)d_in[5];
    const float* Ar   = (const float*)d_in[6];
    const float* br   = (const float*)d_in[7];
    const float* bng  = (const float*)d_in[8];
    const float* bnb  = (const float*)d_in[9];
    const float* dW0  = (const float*)d_in[10];
    const float* db0  = (const float*)d_in[11];
    const float* dW1  = (const float*)d_in[12];
    const float* db1  = (const float*)d_in[13];
    const float* dbng = (const float*)d_in[14];
    const float* dbnb = (const float*)d_in[15];
    const float* W2   = (const float*)d_in[16];
    const float* b2   = (const float*)d_in[17];
    float* out = (float*)d_out;

    const int L_SMEM  = (2048 + 256 * XS + 129 * 64 + 256 * 3 + 1024 + 192) * 4;
    const int D0_SMEM = (64 * 256 + 256 * 128) * 4;

    cudaFuncSetAttribute(layer_kernel<33, 2, true>,
                         cudaFuncAttributeMaxDynamicSharedMemorySize, L_SMEM);
    cudaFuncSetAttribute(layer_kernel<64, 4, false>,
                         cudaFuncAttributeMaxDynamicSharedMemorySize, L_SMEM);
    cudaFuncSetAttribute(dense0_kernel,
                         cudaFuncAttributeMaxDynamicSharedMemorySize, D0_SMEM);

    float* xptr_d0; cudaGetSymbolAddress((void**)&xptr_d0, g_x0);
    float* xptr_d1; cudaGetSymbolAddress((void**)&xptr_d1, g_x1);

    dim3 grid(2, 64);
    // layer 0: xx -> g_x0
    layer_kernel<33, 2, true><<<grid, 512, L_SMEM>>>(
        xx, emb1, emb2, emb3, A0, b0, bng, bnb, nullptr, xptr_d0);
    // layers 1..4 ping-pong: x0->x1->x0->x1->x0
    const float* src[4] = { xptr_d0, xptr_d1, xptr_d0, xptr_d1 };
    float*       dst[4] = { xptr_d1, xptr_d0, xptr_d1, xptr_d0 };
    for (int l = 0; l < 4; l++) {
        layer_kernel<64, 4, false><<<grid, 512, L_SMEM>>>(
            xx, nullptr, nullptr, nullptr,
            Ar + l * 129 * 64, br + l * 64,
            bng + (l + 1) * 64, bnb + (l + 1) * 64,
            src[l], dst[l]);
    }
    dense0_kernel<<<128, 256, D0_SMEM>>>(dW0);
    finalize_kernel<<<64, 128>>>(db0, dW1, db1, dbng, dbnb, W2, b2, out);
}

// round 4
// speedup vs baseline: 1.6190x; 1.0064x over previous
#include <cuda_runtime.h>
#include <math.h>

// 1/sqrt(1 + 1e-3)
#define ISRC 0.9995003746877732f
#define XS 65   // padded row stride of x in smem (bank-conflict-free column reads)

typedef unsigned long long ull;

// scratch (static __device__ arrays: allocation-free)
__device__ float g_x0[64 * 32768];       // ping
__device__ float g_x1[64 * 32768];       // pong
__device__ float g_part[128 * 64 * 128]; // split-K partials: (kchunk, b, d)

// ---------------- f32x2 helpers (Blackwell packed fp32) ----------------
__device__ __forceinline__ ull pk2(float a, float b) {
    ull r; asm("mov.b64 %0,{%1,%2};" : "=l"(r) : "f"(a), "f"(b)); return r;
}
__device__ __forceinline__ void up2(ull p, float& a, float& b) {
    asm("mov.b64 {%0,%1},%2;" : "=f"(a), "=f"(b) : "l"(p));
}
__device__ __forceinline__ ull add2(ull a, ull b) {
    ull r; asm("add.rn.f32x2 %0,%1,%2;" : "=l"(r) : "l"(a), "l"(b)); return r;
}
__device__ __forceinline__ ull mul2(ull a, ull b) {
    ull r; asm("mul.rn.f32x2 %0,%1,%2;" : "=l"(r) : "l"(a), "l"(b)); return r;
}
__device__ __forceinline__ ull fma2_(ull a, ull b, ull c) {
    ull r; asm("fma.rn.f32x2 %0,%1,%2,%3;" : "=l"(r) : "l"(a), "l"(b), "l"(c));
    return r;
}

// ----------------------------------------------------------------------------
// One GNN layer, 2 CTAs per batch (each owns 256 rows). x ping-pongs through
// global memory (stays L2-resident). c (last ND feats of all 512 rows) is read
// directly from the previous layer's global x / from xx for the first layer.
//   y[i,o] = sum_k x[i,k]*A[k,o] + (m_i*S_i-1)*sum_k x[i,k]*A[F+k,o]
//            + (m_i*T_i)*A[2F,o] + b[o],  then *m_i, BN, tanh
// ----------------------------------------------------------------------------
template <int F, int ND, bool FIRST>
__global__ __launch_bounds__(512, 1) void layer_kernel(
    const float* __restrict__ xx,
    const float* __restrict__ e1, const float* __restrict__ e2,
    const float* __restrict__ e3,
    const float* __restrict__ A, const float* __restrict__ bias,
    const float* __restrict__ bng, const float* __restrict__ bnb,
    const float* __restrict__ xin, float* __restrict__ xout)
{
    extern __shared__ float sm[];
    float* c_s  = sm;                 // 512*4 (16B aligned at base)
    float* x_s  = c_s + 2048;         // 256*XS
    float* A_s  = x_s + 256 * XS;     // up to 129*64
    float* m_s  = A_s + 129 * 64;     // 256
    float* s_s  = m_s + 256;          // 256
    float* t_s  = s_s + 256;          // 256
    float* sp   = t_s + 256;          // 512
    float* tp   = sp + 512;           // 512
    float* cn_s = tp + 512;           // 192

    const int b   = blockIdx.y;
    const int h   = blockIdx.x;       // row half: rows [h*256, h*256+256)
    const int tid = threadIdx.x;
    constexpr int KT = 2 * F + 1;

    // ---- stage weights / constants ----
    for (int idx = tid; idx < KT * 64; idx += 512) A_s[idx] = A[idx];
    if (tid < 64) {
        cn_s[tid]       = bias[tid];
        cn_s[64 + tid]  = bng[tid] * ISRC;
        cn_s[128 + tid] = bnb[tid];
    }
    if (tid < 256)
        m_s[tid] = xx[((size_t)b * 512 + h * 256 + tid) * 30];

    if (FIRST) {
        // c for ALL 512 rows comes straight from xx cols 25,26 (== x[31],x[32])
        const float* row = xx + ((size_t)b * 512 + tid) * 30;
        float4 cv; cv.x = row[25]; cv.y = row[26]; cv.z = 0.f; cv.w = 0.f;
        reinterpret_cast<float4*>(c_s)[tid] = cv;
        // build own 256 rows of 33 features
        if (tid < 256) {
            const float* r = xx + ((size_t)b * 512 + h * 256 + tid) * 30;
            int i1 = (int)fabsf(r[27]);
            int i2 = (int)fabsf(r[28]);
            int i3 = (int)fabsf(r[29]);
            float* xr = x_s + tid * XS;
            xr[0] = e1[2 * i1]; xr[1] = e1[2 * i1 + 1];
            xr[2] = e2[2 * i2]; xr[3] = e2[2 * i2 + 1];
            xr[4] = e3[2 * i3]; xr[5] = e3[2 * i3 + 1];
#pragma unroll
            for (int k = 0; k < 27; k++) xr[6 + k] = r[k];
        }
    } else {
        // c for all 512 rows: last 4 feats (cols 60..63, 16B aligned)
        {
            const float* src = xin + ((size_t)b * 512 + tid) * 64;
            reinterpret_cast<float4*>(c_s)[tid] =
                *reinterpret_cast<const float4*>(src + 60);
        }
        // own 256 rows of x (vector global loads, scalar smem stores)
        for (int idx = tid; idx < 4096; idx += 512) {
            int r = idx >> 4, cq = (idx & 15) * 4;
            float4 v = *reinterpret_cast<const float4*>(
                xin + ((size_t)b * 512 + h * 256 + r) * 64 + cq);
            float* d = x_s + r * XS + cq;
            d[0] = v.x; d[1] = v.y; d[2] = v.z; d[3] = v.w;
        }
    }
    __syncthreads();

    // ---- pairwise S/T: thread (i = tid&255) handles j-half (tid>>8) ----
    {
        const int i  = tid & 255;
        const int jh = tid >> 8;
        const float4 ci = reinterpret_cast<const float4*>(c_s)[h * 256 + i];
        const ull ni01 = pk2(-ci.x, -ci.y);
        const ull ni23 = pk2(-ci.z, -ci.w);
        const ulonglong2* cp = reinterpret_cast<const ulonglong2*>(c_s);
        float S = 0.f, T = 0.f;
#pragma unroll 8
        for (int j = jh * 256; j < jh * 256 + 256; j++) {
            ulonglong2 cj = cp[j];
            ull dxy = add2(cj.x, ni01);
            ull q = mul2(dxy, dxy);
            if (ND == 4) {
                ull dzw = add2(cj.y, ni23);
                q = fma2_(dzw, dzw, q);
            }
            float qlo, qhi; up2(q, qlo, qhi);
            float d = qlo + qhi;
            float w = __expf(-10.f * d);
            S += w;
            T = fmaf(d, w, T);
        }
        sp[tid] = S; tp[tid] = T;
    }
    __syncthreads();
    if (tid < 256) {
        float S = sp[tid] + sp[tid + 256];
        float T = tp[tid] + tp[tid + 256];
        float m = m_s[tid];
        s_s[tid] = fmaf(m, S, -1.f);   // (m*S - 1)
        t_s[tid] = m * T;
    }
    __syncthreads();

    // ---- GEMM: each thread 4 rows x 8 cols, packed f32x2 FMAs ----
    const int cs0 = (tid & 7) * 8;
    const int r0  = (tid >> 3) * 4;    // local rows r0..r0+3
    ull u[4][4], v[4][4];
#pragma unroll
    for (int r = 0; r < 4; r++)
#pragma unroll
        for (int c = 0; c < 4; c++) { u[r][c] = 0ull; v[r][c] = 0ull; }

    const float* xr0 = x_s + (r0 + 0) * XS;
    const float* xr1 = x_s + (r0 + 1) * XS;
    const float* xr2 = x_s + (r0 + 2) * XS;
    const float* xr3 = x_s + (r0 + 3) * XS;

#pragma unroll 4
    for (int k = 0; k < F; k++) {
        ulonglong2 a01 = *reinterpret_cast<const ulonglong2*>(&A_s[k * 64 + cs0]);
        ulonglong2 a23 = *reinterpret_cast<const ulonglong2*>(&A_s[k * 64 + cs0 + 4]);
        ulonglong2 q01 = *reinterpret_cast<const ulonglong2*>(&A_s[(F + k) * 64 + cs0]);
        ulonglong2 q23 = *reinterpret_cast<const ulonglong2*>(&A_s[(F + k) * 64 + cs0 + 4]);
        ull xp[4];
        { float xv = xr0[k]; xp[0] = pk2(xv, xv); }
        { float xv = xr1[k]; xp[1] = pk2(xv, xv); }
        { float xv = xr2[k]; xp[2] = pk2(xv, xv); }
        { float xv = xr3[k]; xp[3] = pk2(xv, xv); }
#pragma unroll
        for (int r = 0; r < 4; r++) {
            u[r][0] = fma2_(xp[r], a01.x, u[r][0]);
            u[r][1] = fma2_(xp[r], a01.y, u[r][1]);
            u[r][2] = fma2_(xp[r], a23.x, u[r][2]);
            u[r][3] = fma2_(xp[r], a23.y, u[r][3]);
            v[r][0] = fma2_(xp[r], q01.x, v[r][0]);
            v[r][1] = fma2_(xp[r], q01.y, v[r][1]);
            v[r][2] = fma2_(xp[r], q23.x, v[r][2]);
            v[r][3] = fma2_(xp[r], q23.y, v[r][3]);
        }
    }

    // ---- epilogue: combine, bias, mask, BN, tanh, store to global ----
#pragma unroll
    for (int r = 0; r < 4; r++) {
        const int i = r0 + r;
        const float s = s_s[i], t = t_s[i], m = m_s[i];
        const ull s2 = pk2(s, s);
        float o[8];
#pragma unroll
        for (int cp2 = 0; cp2 < 4; cp2++) {
            ull y2 = fma2_(s2, v[r][cp2], u[r][cp2]);
            float ylo, yhi; up2(y2, ylo, yhi);
            const int c = cs0 + cp2 * 2;
            float a0 = fmaf(t, A_s[2 * F * 64 + c], ylo) + cn_s[c];
            float a1 = fmaf(t, A_s[2 * F * 64 + c + 1], yhi) + cn_s[c + 1];
            a0 *= m; a1 *= m;
            o[cp2 * 2]     = tanhf(fmaf(cn_s[64 + c], a0, cn_s[128 + c]));
            o[cp2 * 2 + 1] = tanhf(fmaf(cn_s[64 + c + 1], a1, cn_s[128 + c + 1]));
        }
        float4* dst = reinterpret_cast<float4*>(
            xout + ((size_t)b * 512 + h * 256 + i) * 64 + cs0);
        dst[0] = make_float4(o[0], o[1], o[2], o[3]);
        dst[1] = make_float4(o[4], o[5], o[6], o[7]);
    }
}

// ----------------------------------------------------------------------------
// Dense layer 0 split-K: 128 CTAs, each owns a K-chunk of 256.
// Deterministic: partials stored, reduced in finalize (no float atomics).
// ----------------------------------------------------------------------------
__global__ __launch_bounds__(256, 1) void dense0_kernel(const float* __restrict__ W)
{
    extern __shared__ float sm[];
    float* Xs = sm;              // 64 x 256
    float* Ws = Xs + 64 * 256;   // 256 x 128
    const int tid = threadIdx.x;
    const int kc  = blockIdx.x;

    for (int idx = tid; idx < 64 * 256; idx += 256) {
        int b = idx >> 8, k = idx & 255;
        Xs[idx] = g_x0[(size_t)b * 32768 + kc * 256 + k];
    }
    const float* wsrc = W + (size_t)kc * 256 * 128;
    for (int idx = tid; idx < 256 * 128; idx += 256) Ws[idx] = wsrc[idx];
    __syncthreads();

    const int bs = tid >> 5;   // 0..7  -> rows b = bs*8..bs*8+7
    const int ds = tid & 31;   // 0..31 -> cols d = ds*4..ds*4+3
    float acc[8][4];
#pragma unroll
    for (int r = 0; r < 8; r++)
#pragma unroll
        for (int j = 0; j < 4; j++) acc[r][j] = 0.f;

#pragma unroll 4
    for (int k = 0; k < 256; k++) {
        float4 w4 = *reinterpret_cast<const float4*>(&Ws[k * 128 + ds * 4]);
#pragma unroll
        for (int r = 0; r < 8; r++) {
            float xv = Xs[(bs * 8 + r) * 256 + k];  // warp-broadcast
            acc[r][0] = fmaf(xv, w4.x, acc[r][0]);
            acc[r][1] = fmaf(xv, w4.y, acc[r][1]);
            acc[r][2] = fmaf(xv, w4.z, acc[r][2]);
            acc[r][3] = fmaf(xv, w4.w, acc[r][3]);
        }
    }
    float* dst = g_part + (size_t)kc * 8192;
#pragma unroll
    for (int r = 0; r < 8; r++)
#pragma unroll
        for (int j = 0; j < 4; j++)
            dst[(bs * 8 + r) * 128 + ds * 4 + j] = acc[r][j];
}

// ----------------------------------------------------------------------------
// Finalize: reduce partials, BN+sigmoid, dense1, BN+sigmoid, W2, write (64,4)
// ----------------------------------------------------------------------------
__global__ __launch_bounds__(128, 1) void finalize_kernel(
    const float* __restrict__ db0, const float* __restrict__ dW1,
    const float* __restrict__ db1, const float* __restrict__ dbng,
    const float* __restrict__ dbnb, const float* __restrict__ W2,
    const float* __restrict__ b2, float* __restrict__ out)
{
    __shared__ float h0[128];
    __shared__ float h1[128];
    const int b = blockIdx.x;
    const int d = threadIdx.x;

    float a = db0[d];
#pragma unroll 4
    for (int kc = 0; kc < 128; kc++) a += g_part[(size_t)kc * 8192 + b * 128 + d];
    a = fmaf(dbng[d] * ISRC, a, dbnb[d]);
    h0[d] = 1.f / (1.f + __expf(-a));
    __syncthreads();

    float s = 0.f;
#pragma unroll 8
    for (int k = 0; k < 128; k++) s = fmaf(h0[k], dW1[k * 128 + d], s);
    s += db1[d];
    s = fmaf(dbng[128 + d] * ISRC, s, dbnb[128 + d]);
    h1[d] = 1.f / (1.f + __expf(-s));
    __syncthreads();

    if (d < 4) {
        float o = 0.f;
        if (d < 2) {
            o = b2[d];
            for (int k = 0; k < 128; k++) o = fmaf(h1[k], W2[k * 2 + d], o);
        }
        out[b * 4 + d] = o;
    }
}

// ----------------------------------------------------------------------------
extern "C" void kernel_launch(void* const* d_in, const int* in_sizes, int n_in,
                              void* d_out, int out_size)
{
    const float* xx   = (const float*)d_in[0];
    const float* emb1 = (const float*)d_in[1];
    const float* emb2 = (const float*)d_in[2];
    const float* emb3 = (const float*)d_in[3];
    const float* A0   = (const float*)d_in[4];
    const float* b0   = (const float*)d_in[5];
    const float* Ar   = (const float*)d_in[6];
    const float* br   = (const float*)d_in[7];
    const float* bng  = (const float*)d_in[8];
    const float* bnb  = (const float*)d_in[9];
    const float* dW0  = (const float*)d_in[10];
    const float* db0  = (const float*)d_in[11];
    const float* dW1  = (const float*)d_in[12];
    const float* db1  = (const float*)d_in[13];
    const float* dbng = (const float*)d_in[14];
    const float* dbnb = (const float*)d_in[15];
    const float* W2   = (const float*)d_in[16];
    const float* b2   = (const float*)d_in[17];
    float* out = (float*)d_out;

    const int L_SMEM  = (2048 + 256 * XS + 129 * 64 + 256 * 3 + 1024 + 192) * 4;
    const int D0_SMEM = (64 * 256 + 256 * 128) * 4;

    cudaFuncSetAttribute(layer_kernel<33, 2, true>,
                         cudaFuncAttributeMaxDynamicSharedMemorySize, L_SMEM);
    cudaFuncSetAttribute(layer_kernel<64, 4, false>,
                         cudaFuncAttributeMaxDynamicSharedMemorySize, L_SMEM);
    cudaFuncSetAttribute(dense0_kernel,
                         cudaFuncAttributeMaxDynamicSharedMemorySize, D0_SMEM);

    float* xptr_d0; cudaGetSymbolAddress((void**)&xptr_d0, g_x0);
    float* xptr_d1; cudaGetSymbolAddress((void**)&xptr_d1, g_x1);

    dim3 grid(2, 64);
    // layer 0: xx -> g_x0
    layer_kernel<33, 2, true><<<grid, 512, L_SMEM>>>(
        xx, emb1, emb2, emb3, A0, b0, bng, bnb, nullptr, xptr_d0);
    // layers 1..4 ping-pong: x0->x1->x0->x1->x0
    const float* src[4] = { xptr_d0, xptr_d1, xptr_d0, xptr_d1 };
    float*       dst[4] = { xptr_d1, xptr_d0, xptr_d1, xptr_d0 };
    for (int l = 0; l < 4; l++) {
        layer_kernel<64, 4, false><<<grid, 512, L_SMEM>>>(
            xx, nullptr, nullptr, nullptr,
            Ar + l * 129 * 64, br + l * 64,
            bng + (l + 1) * 64, bnb + (l + 1) * 64,
            src[l], dst[l]);
    }
    dense0_kernel<<<128, 256, D0_SMEM>>>(dW0);
    finalize_kernel<<<64, 128>>>(db0, dW1, db1, dbng, dbnb, W2, b2, out);
}

// round 10
// speedup vs baseline: 1.7491x; 1.0804x over previous
#include <cuda_runtime.h>
#include <stdint.h>
#include <math.h>

// 1/sqrt(1 + 1e-3)
#define ISRC 0.9995003746877732f
#define XS 68   // x row stride (floats): 16B-aligned rows, low bank conflicts

typedef unsigned long long ull;

// scratch (static __device__ arrays: allocation-free)
__device__ float g_x0[64 * 32768];       // GNN output, (B, N*64) row-major
__device__ float g_part[128 * 64 * 128]; // split-K partials: (kchunk, b, d)

// ---------------- f32x2 helpers (Blackwell packed fp32) ----------------
__device__ __forceinline__ ull pk2(float a, float b) {
    ull r; asm("mov.b64 %0,{%1,%2};" : "=l"(r) : "f"(a), "f"(b)); return r;
}
__device__ __forceinline__ void up2(ull p, float& a, float& b) {
    asm("mov.b64 {%0,%1},%2;" : "=f"(a), "=f"(b) : "l"(p));
}
__device__ __forceinline__ ull add2(ull a, ull b) {
    ull r; asm("add.rn.f32x2 %0,%1,%2;" : "=l"(r) : "l"(a), "l"(b)); return r;
}
__device__ __forceinline__ ull mul2(ull a, ull b) {
    ull r; asm("mul.rn.f32x2 %0,%1,%2;" : "=l"(r) : "l"(a), "l"(b)); return r;
}
__device__ __forceinline__ ull fma2_(ull a, ull b, ull c) {
    ull r; asm("fma.rn.f32x2 %0,%1,%2,%3;" : "=l"(r) : "l"(a), "l"(b), "l"(c));
    return r;
}

// ---------------- cluster / DSMEM helpers ----------------
__device__ __forceinline__ uint32_t smem_u32(const void* p) {
    uint32_t a;
    asm("{ .reg .u64 t; cvta.to.shared.u64 t, %1; cvt.u32.u64 %0, t; }"
        : "=r"(a) : "l"(p));
    return a;
}
__device__ __forceinline__ void cluster_sync_() {
    asm volatile("barrier.cluster.arrive.aligned;" ::: "memory");
    asm volatile("barrier.cluster.wait.aligned;" ::: "memory");
}
__device__ __forceinline__ uint32_t mapa_(uint32_t local, uint32_t rank) {
    uint32_t r;
    asm("mapa.shared::cluster.u32 %0, %1, %2;" : "=r"(r) : "r"(local), "r"(rank));
    return r;
}
__device__ __forceinline__ float4 dsmem_ld4(uint32_t addr) {
    float4 v;
    asm volatile("ld.shared::cluster.v4.f32 {%0,%1,%2,%3}, [%4];"
                 : "=f"(v.x), "=f"(v.y), "=f"(v.z), "=f"(v.w) : "r"(addr));
    return v;
}

// ---------------- pairwise S/T over all 512 j (thread = (i, j-half)) -------
__device__ __forceinline__ void pairwise(const float* c_s, float* sp, float* tp,
                                         int tid, int h)
{
    const int i  = tid & 255;
    const int jh = tid >> 8;
    const float4 ci = reinterpret_cast<const float4*>(c_s)[h * 256 + i];
    const ull ni01 = pk2(-ci.x, -ci.y);
    const ull ni23 = pk2(-ci.z, -ci.w);
    const ulonglong2* cp = reinterpret_cast<const ulonglong2*>(c_s);
    float S = 0.f, T = 0.f;
#pragma unroll 8
    for (int j = jh * 256; j < jh * 256 + 256; j++) {
        ulonglong2 cj = cp[j];
        ull dxy = add2(cj.x, ni01);
        ull q = mul2(dxy, dxy);
        ull dzw = add2(cj.y, ni23);
        q = fma2_(dzw, dzw, q);
        float ql, qh; up2(q, ql, qh);
        float d = ql + qh;
        float w = __expf(-10.f * d);
        S += w;
        T = fmaf(d, w, T);
    }
    sp[tid] = S; tp[tid] = T;
}

// ---------------- GEMM + epilogue into registers ---------------------------
// y[i,o] = sum_k x[i,k]*A[k,o] + s_i*sum_k x[i,k]*A[FP+k,o] + t_i*A[2FP,o]
//          + bias[o], then *m_i, BN, tanh
template <int FP>
__device__ __forceinline__ void gemm_epi(
    const float* x_s, const float* A_s, const float* s_s, const float* t_s,
    const float* m_s, const float* cn_s, int tid, float o[4][8])
{
    const int cs0 = (tid & 7) * 8;
    const int r0  = (tid >> 3) * 4;
    ull u[4][4], v[4][4];
#pragma unroll
    for (int r = 0; r < 4; r++)
#pragma unroll
        for (int c = 0; c < 4; c++) { u[r][c] = 0ull; v[r][c] = 0ull; }

    const float* xb = x_s + r0 * XS;
#pragma unroll 2
    for (int kq = 0; kq < FP / 4; kq++) {
        float xq[4][4];
#pragma unroll
        for (int r = 0; r < 4; r++)
            *reinterpret_cast<float4*>(xq[r]) =
                *reinterpret_cast<const float4*>(xb + r * XS + kq * 4);
#pragma unroll
        for (int j = 0; j < 4; j++) {
            const int k = kq * 4 + j;
            ulonglong2 a01 = *reinterpret_cast<const ulonglong2*>(&A_s[k * 64 + cs0]);
            ulonglong2 a23 = *reinterpret_cast<const ulonglong2*>(&A_s[k * 64 + cs0 + 4]);
            ulonglong2 q01 = *reinterpret_cast<const ulonglong2*>(&A_s[(FP + k) * 64 + cs0]);
            ulonglong2 q23 = *reinterpret_cast<const ulonglong2*>(&A_s[(FP + k) * 64 + cs0 + 4]);
#pragma unroll
            for (int r = 0; r < 4; r++) {
                ull xp = pk2(xq[r][j], xq[r][j]);
                u[r][0] = fma2_(xp, a01.x, u[r][0]);
                u[r][1] = fma2_(xp, a01.y, u[r][1]);
                u[r][2] = fma2_(xp, a23.x, u[r][2]);
                u[r][3] = fma2_(xp, a23.y, u[r][3]);
                v[r][0] = fma2_(xp, q01.x, v[r][0]);
                v[r][1] = fma2_(xp, q01.y, v[r][1]);
                v[r][2] = fma2_(xp, q23.x, v[r][2]);
                v[r][3] = fma2_(xp, q23.y, v[r][3]);
            }
        }
    }
#pragma unroll
    for (int r = 0; r < 4; r++) {
        const int i = r0 + r;
        const float s = s_s[i], t = t_s[i], m = m_s[i];
        const ull s2 = pk2(s, s);
#pragma unroll
        for (int c2 = 0; c2 < 4; c2++) {
            ull y2 = fma2_(s2, v[r][c2], u[r][c2]);
            float yl, yh; up2(y2, yl, yh);
            const int c = cs0 + c2 * 2;
            float a0 = (fmaf(t, A_s[2 * FP * 64 + c],     yl) + cn_s[c])     * m;
            float a1 = (fmaf(t, A_s[2 * FP * 64 + c + 1], yh) + cn_s[c + 1]) * m;
            o[r][c2 * 2]     = tanhf(fmaf(cn_s[64 + c],     a0, cn_s[128 + c]));
            o[r][c2 * 2 + 1] = tanhf(fmaf(cn_s[64 + c + 1], a1, cn_s[128 + c + 1]));
        }
    }
}

// ----------------------------------------------------------------------------
// Fused GNN: all 5 layers in one kernel. Cluster of 2 CTAs per batch; each CTA
// owns 256 rows resident in SMEM; per-layer c vector exchanged via DSMEM.
// ----------------------------------------------------------------------------
__global__ __launch_bounds__(512, 1) __cluster_dims__(2, 1, 1)
void gnn_fused_kernel(
    const float* __restrict__ xx,
    const float* __restrict__ e1, const float* __restrict__ e2,
    const float* __restrict__ e3,
    const float* __restrict__ A0, const float* __restrict__ b0,
    const float* __restrict__ Ar, const float* __restrict__ br,
    const float* __restrict__ bng, const float* __restrict__ bnb)
{
    extern __shared__ float sm[];
    float* c_s  = sm;                 // 512*4 (16B aligned)
    float* x_s  = c_s + 2048;         // 256*XS
    float* A_s  = x_s + 256 * XS;     // 129*64 max
    float* m_s  = A_s + 129 * 64;     // 256
    float* s_s  = m_s + 256;          // 256
    float* t_s  = s_s + 256;          // 256
    float* sp   = t_s + 256;          // 512
    float* tp   = sp + 512;           // 512
    float* cn_s = tp + 512;           // 192

    const int h   = blockIdx.x;       // rank in cluster (row half)
    const int b   = blockIdx.y;
    const int tid = threadIdx.x;
    const uint32_t c_u32 = smem_u32(c_s);

    // ---- init: mask, layer-0 features (FP=36, cols 33..35 zero), c from xx --
    if (tid < 256) {
        const float* r = xx + ((size_t)b * 512 + h * 256 + tid) * 30;
        m_s[tid] = r[0];
        int i1 = (int)fabsf(r[27]);
        int i2 = (int)fabsf(r[28]);
        int i3 = (int)fabsf(r[29]);
        float* xr = x_s + tid * XS;
        xr[0] = e1[2 * i1]; xr[1] = e1[2 * i1 + 1];
        xr[2] = e2[2 * i2]; xr[3] = e2[2 * i2 + 1];
        xr[4] = e3[2 * i3]; xr[5] = e3[2 * i3 + 1];
#pragma unroll
        for (int k = 0; k < 27; k++) xr[6 + k] = r[k];
        xr[33] = 0.f; xr[34] = 0.f; xr[35] = 0.f;
    }
    {   // layer-0 c for ALL 512 rows straight from xx (no exchange needed)
        const float* row = xx + ((size_t)b * 512 + tid) * 30;
        float4 cv; cv.x = row[25]; cv.y = row[26]; cv.z = 0.f; cv.w = 0.f;
        reinterpret_cast<float4*>(c_s)[tid] = cv;
    }
    // stage A0 padded to FP=36 (zero rows 33..35, 69..71; tail at 72)
    for (int idx = tid; idx < 73 * 64; idx += 512) {
        int kp = idx >> 6, c = idx & 63;
        float val = 0.f;
        if (kp < 33)                  val = A0[kp * 64 + c];
        else if (kp >= 36 && kp < 69) val = A0[(kp - 3) * 64 + c];
        else if (kp == 72)            val = A0[66 * 64 + c];
        A_s[idx] = val;
    }
    if (tid < 64) {
        cn_s[tid]       = b0[tid];
        cn_s[64 + tid]  = bng[tid] * ISRC;
        cn_s[128 + tid] = bnb[tid];
    }
    __syncthreads();

    // ---- layer 0 ----
    {
        pairwise(c_s, sp, tp, tid, h);
        __syncthreads();
        if (tid < 256) {
            float m = m_s[tid];
            s_s[tid] = fmaf(m, sp[tid] + sp[tid + 256], -1.f);
            t_s[tid] = m * (tp[tid] + tp[tid + 256]);
        }
        __syncthreads();
        float o[4][8];
        gemm_epi<36>(x_s, A_s, s_s, t_s, m_s, cn_s, tid, o);
        __syncthreads();   // all x_s reads of this layer done
        const int cs0 = (tid & 7) * 8, r0 = (tid >> 3) * 4;
#pragma unroll
        for (int r = 0; r < 4; r++) {
            float4* dst = reinterpret_cast<float4*>(x_s + (r0 + r) * XS + cs0);
            dst[0] = make_float4(o[r][0], o[r][1], o[r][2], o[r][3]);
            dst[1] = make_float4(o[r][4], o[r][5], o[r][6], o[r][7]);
        }
        __syncthreads();   // new x visible
    }

    // ---- layers 1..4 ----
#pragma unroll 1
    for (int l = 0; l < 4; l++) {
        // stage layer weights + constants
        const float* A = Ar + l * 129 * 64;
        for (int idx = tid; idx < 129 * 64; idx += 512) A_s[idx] = A[idx];
        if (tid < 64) {
            cn_s[tid]       = br[l * 64 + tid];
            cn_s[64 + tid]  = bng[(l + 1) * 64 + tid] * ISRC;
            cn_s[128 + tid] = bnb[(l + 1) * 64 + tid];
        }
        // own c half: last 4 feats of own rows
        if (tid < 256) {
            const float* xr = x_s + tid * XS;
            float4 cv; cv.x = xr[60]; cv.y = xr[61]; cv.z = xr[62]; cv.w = xr[63];
            reinterpret_cast<float4*>(c_s)[h * 256 + tid] = cv;
        }
        cluster_sync_();               // both halves of c written & visible
        if (tid < 256) {               // fetch peer half via DSMEM
            const int ph = 1 - h;
            uint32_t la = c_u32 + (uint32_t)(ph * 256 + tid) * 16u;
            float4 v = dsmem_ld4(mapa_(la, (uint32_t)ph));
            reinterpret_cast<float4*>(c_s)[ph * 256 + tid] = v;
        }
        cluster_sync_();               // both copies done -> c_s stable
        __syncthreads();

        pairwise(c_s, sp, tp, tid, h);
        __syncthreads();
        if (tid < 256) {
            float m = m_s[tid];
            s_s[tid] = fmaf(m, sp[tid] + sp[tid + 256], -1.f);
            t_s[tid] = m * (tp[tid] + tp[tid + 256]);
        }
        __syncthreads();

        float o[4][8];
        gemm_epi<64>(x_s, A_s, s_s, t_s, m_s, cn_s, tid, o);

        const int cs0 = (tid & 7) * 8, r0 = (tid >> 3) * 4;
        if (l < 3) {
            __syncthreads();   // all x_s reads done before overwrite
#pragma unroll
            for (int r = 0; r < 4; r++) {
                float4* dst = reinterpret_cast<float4*>(x_s + (r0 + r) * XS + cs0);
                dst[0] = make_float4(o[r][0], o[r][1], o[r][2], o[r][3]);
                dst[1] = make_float4(o[r][4], o[r][5], o[r][6], o[r][7]);
            }
            __syncthreads();   // new x visible
        } else {
            // last layer: write straight to global for the dense head
#pragma unroll
            for (int r = 0; r < 4; r++) {
                float4* dst = reinterpret_cast<float4*>(
                    g_x0 + (size_t)b * 32768 + (h * 256 + r0 + r) * 64 + cs0);
                dst[0] = make_float4(o[r][0], o[r][1], o[r][2], o[r][3]);
                dst[1] = make_float4(o[r][4], o[r][5], o[r][6], o[r][7]);
            }
        }
    }
}

// ----------------------------------------------------------------------------
// Dense layer 0 split-K: 128 CTAs, each owns a K-chunk of 256. f32x2 packed.
// Deterministic: partials stored, reduced in finalize (no float atomics).
// ----------------------------------------------------------------------------
#define D0XS 257
__global__ __launch_bounds__(256, 1) void dense0_kernel(const float* __restrict__ W)
{
    extern __shared__ float sm[];
    float* Xs = sm;                 // 64 x 257 (padded)
    float* Ws = Xs + 64 * D0XS;     // 256 x 128
    const int tid = threadIdx.x;
    const int kc  = blockIdx.x;

    for (int idx = tid; idx < 64 * 256; idx += 256) {
        int bb = idx >> 8, k = idx & 255;
        Xs[bb * D0XS + k] = g_x0[(size_t)bb * 32768 + kc * 256 + k];
    }
    const float* wsrc = W + (size_t)kc * 256 * 128;
    for (int idx = tid; idx < 256 * 128 / 4; idx += 256)
        reinterpret_cast<float4*>(Ws)[idx] =
            reinterpret_cast<const float4*>(wsrc)[idx];
    __syncthreads();

    const int rg = tid >> 4;   // 0..15 -> rows rg*4..rg*4+3
    const int cg = tid & 15;   // 0..15 -> cols cg*8..cg*8+7
    ull acc[4][4];
#pragma unroll
    for (int r = 0; r < 4; r++)
#pragma unroll
        for (int c = 0; c < 4; c++) acc[r][c] = 0ull;

#pragma unroll 2
    for (int k = 0; k < 256; k++) {
        ulonglong2 w01 = *reinterpret_cast<const ulonglong2*>(&Ws[k * 128 + cg * 8]);
        ulonglong2 w23 = *reinterpret_cast<const ulonglong2*>(&Ws[k * 128 + cg * 8 + 4]);
#pragma unroll
        for (int r = 0; r < 4; r++) {
            float xv = Xs[(rg * 4 + r) * D0XS + k];
            ull xp = pk2(xv, xv);
            acc[r][0] = fma2_(xp, w01.x, acc[r][0]);
            acc[r][1] = fma2_(xp, w01.y, acc[r][1]);
            acc[r][2] = fma2_(xp, w23.x, acc[r][2]);
            acc[r][3] = fma2_(xp, w23.y, acc[r][3]);
        }
    }
    float* dst = g_part + (size_t)kc * 8192;
#pragma unroll
    for (int r = 0; r < 4; r++) {
        ulonglong2* d = reinterpret_cast<ulonglong2*>(&dst[(rg * 4 + r) * 128 + cg * 8]);
        d[0] = make_ulonglong2(acc[r][0], acc[r][1]);
        d[1] = make_ulonglong2(acc[r][2], acc[r][3]);
    }
}

// ----------------------------------------------------------------------------
// Finalize: reduce partials, BN+sigmoid, dense1, BN+sigmoid, W2, write (64,4)
// ----------------------------------------------------------------------------
__global__ __launch_bounds__(128, 1) void finalize_kernel(
    const float* __restrict__ db0, const float* __restrict__ dW1,
    const float* __restrict__ db1, const float* __restrict__ dbng,
    const float* __restrict__ dbnb, const float* __restrict__ W2,
    const float* __restrict__ b2, float* __restrict__ out)
{
    __shared__ float h0[128];
    __shared__ float h1[128];
    const int b = blockIdx.x;
    const int d = threadIdx.x;

    float a = db0[d];
#pragma unroll 4
    for (int kc = 0; kc < 128; kc++) a += g_part[(size_t)kc * 8192 + b * 128 + d];
    a = fmaf(dbng[d] * ISRC, a, dbnb[d]);
    h0[d] = 1.f / (1.f + __expf(-a));
    __syncthreads();

    float s = 0.f;
#pragma unroll 8
    for (int k = 0; k < 128; k++) s = fmaf(h0[k], dW1[k * 128 + d], s);
    s += db1[d];
    s = fmaf(dbng[128 + d] * ISRC, s, dbnb[128 + d]);
    h1[d] = 1.f / (1.f + __expf(-s));
    __syncthreads();

    if (d < 4) {
        float o = 0.f;
        if (d < 2) {
            o = b2[d];
            for (int k = 0; k < 128; k++) o = fmaf(h1[k], W2[k * 2 + d], o);
        }
        out[b * 4 + d] = o;
    }
}

// ----------------------------------------------------------------------------
extern "C" void kernel_launch(void* const* d_in, const int* in_sizes, int n_in,
                              void* d_out, int out_size)
{
    const float* xx   = (const float*)d_in[0];
    const float* emb1 = (const float*)d_in[1];
    const float* emb2 = (const float*)d_in[2];
    const float* emb3 = (const float*)d_in[3];
    const float* A0   = (const float*)d_in[4];
    const float* b0   = (const float*)d_in[5];
    const float* Ar   = (const float*)d_in[6];
    const float* br   = (const float*)d_in[7];
    const float* bng  = (const float*)d_in[8];
    const float* bnb  = (const float*)d_in[9];
    const float* dW0  = (const float*)d_in[10];
    const float* db0  = (const float*)d_in[11];
    const float* dW1  = (const float*)d_in[12];
    const float* db1  = (const float*)d_in[13];
    const float* dbng = (const float*)d_in[14];
    const float* dbnb = (const float*)d_in[15];
    const float* W2   = (const float*)d_in[16];
    const float* b2   = (const float*)d_in[17];
    float* out = (float*)d_out;

    const int G_SMEM  = (2048 + 256 * XS + 129 * 64 + 256 * 3 + 1024 + 192) * 4;
    const int D0_SMEM = (64 * D0XS + 256 * 128) * 4;

    cudaFuncSetAttribute(gnn_fused_kernel,
                         cudaFuncAttributeMaxDynamicSharedMemorySize, G_SMEM);
    cudaFuncSetAttribute(dense0_kernel,
                         cudaFuncAttributeMaxDynamicSharedMemorySize, D0_SMEM);

    dim3 grid(2, 64);
    gnn_fused_kernel<<<grid, 512, G_SMEM>>>(
        xx, emb1, emb2, emb3, A0, b0, Ar, br, bng, bnb);
    dense0_kernel<<<128, 256, D0_SMEM>>>(dW0);
    finalize_kernel<<<64, 128>>>(db0, dW1, db1, dbng, dbnb, W2, b2, out);
}

// round 12
// speedup vs baseline: 1.9251x; 1.1006x over previous
#include <cuda_runtime.h>
#include <stdint.h>
#include <math.h>

// 1/sqrt(1 + 1e-3)
#define ISRC 0.9995003746877732f
#define XS 68               // x row stride (floats)
#define KEXP -14.42695040888963f   // -10 * log2(e)

typedef unsigned long long ull;

// scratch (static __device__ arrays: allocation-free)
__device__ float g_x0[64 * 32768];       // GNN output, (B, N*64) row-major
__device__ float g_part[128 * 64 * 128]; // split-K partials: (kchunk, b, d)

// ---------------- f32x2 helpers (Blackwell packed fp32) ----------------
__device__ __forceinline__ ull pk2(float a, float b) {
    ull r; asm("mov.b64 %0,{%1,%2};" : "=l"(r) : "f"(a), "f"(b)); return r;
}
__device__ __forceinline__ void up2(ull p, float& a, float& b) {
    asm("mov.b64 {%0,%1},%2;" : "=f"(a), "=f"(b) : "l"(p));
}
__device__ __forceinline__ ull add2(ull a, ull b) {
    ull r; asm("add.rn.f32x2 %0,%1,%2;" : "=l"(r) : "l"(a), "l"(b)); return r;
}
__device__ __forceinline__ ull mul2(ull a, ull b) {
    ull r; asm("mul.rn.f32x2 %0,%1,%2;" : "=l"(r) : "l"(a), "l"(b)); return r;
}
__device__ __forceinline__ ull fma2_(ull a, ull b, ull c) {
    ull r; asm("fma.rn.f32x2 %0,%1,%2,%3;" : "=l"(r) : "l"(a), "l"(b), "l"(c));
    return r;
}

// ---------------- fast math ----------------
__device__ __forceinline__ float ex2f(float x) {
    float r; asm("ex2.approx.ftz.f32 %0,%1;" : "=f"(r) : "f"(x)); return r;
}
__device__ __forceinline__ float rcpf(float x) {
    float r; asm("rcp.approx.ftz.f32 %0,%1;" : "=f"(r) : "f"(x)); return r;
}
// tanh(y) = 1 - 2/(exp(2y)+1), branchless, saturates correctly at +/-inf
__device__ __forceinline__ float ftanh(float y) {
    float e = ex2f(y * 2.885390081777927f);   // 2*log2(e)
    return fmaf(-2.0f, rcpf(e + 1.0f), 1.0f);
}

// ---------------- cluster / DSMEM helpers ----------------
__device__ __forceinline__ uint32_t smem_u32(const void* p) {
    uint32_t a;
    asm("{ .reg .u64 t; cvta.to.shared.u64 t, %1; cvt.u32.u64 %0, t; }"
        : "=r"(a) : "l"(p));
    return a;
}
__device__ __forceinline__ void cluster_sync_() {
    asm volatile("barrier.cluster.arrive.aligned;" ::: "memory");
    asm volatile("barrier.cluster.wait.aligned;" ::: "memory");
}
__device__ __forceinline__ uint32_t mapa_(uint32_t local, uint32_t rank) {
    uint32_t r;
    asm("mapa.shared::cluster.u32 %0, %1, %2;" : "=r"(r) : "r"(local), "r"(rank));
    return r;
}
__device__ __forceinline__ void st_cluster_f32(uint32_t addr, float v) {
    asm volatile("st.shared::cluster.f32 [%0],%1;" :: "r"(addr), "f"(v) : "memory");
}

// ---------------- pairwise S/T, SoA c, 2 j's per f32x2 lane-pair -----------
// thread = (i = tid&255, j-half = tid>>8); sp/tp hold per-half partials
template <int ND>
__device__ __forceinline__ void pairwise_soa(
    const float* __restrict__ cx, const float* __restrict__ cy,
    const float* __restrict__ cz, const float* __restrict__ cw,
    float* sp, float* tp, int tid, int h)
{
    const int i  = tid & 255;
    const int jh = tid >> 8;
    const int gi = h * 256 + i;
    const float cix = cx[gi], ciy = cy[gi];
    const ull nix = pk2(-cix, -cix);
    const ull niy = pk2(-ciy, -ciy);
    ull niz = 0ull, niw = 0ull;
    if (ND == 4) {
        float ciz = cz[gi], ciw = cw[gi];
        niz = pk2(-ciz, -ciz);
        niw = pk2(-ciw, -ciw);
    }
    const ull K2 = pk2(KEXP, KEXP);
    ull S2a = 0ull, T2a = 0ull, S2b = 0ull, T2b = 0ull;
    const int j0 = jh * 256;
#pragma unroll 4
    for (int j = j0; j < j0 + 256; j += 4) {
        ulonglong2 X = *reinterpret_cast<const ulonglong2*>(cx + j);
        ulonglong2 Y = *reinterpret_cast<const ulonglong2*>(cy + j);
        ull da, db;
        { ull d = add2(X.x, nix); da = mul2(d, d);
          d = add2(Y.x, niy);     da = fma2_(d, d, da); }
        { ull d = add2(X.y, nix); db = mul2(d, d);
          d = add2(Y.y, niy);     db = fma2_(d, d, db); }
        if (ND == 4) {
            ulonglong2 Z = *reinterpret_cast<const ulonglong2*>(cz + j);
            ulonglong2 W = *reinterpret_cast<const ulonglong2*>(cw + j);
            { ull d = add2(Z.x, niz); da = fma2_(d, d, da);
              d = add2(W.x, niw);     da = fma2_(d, d, da); }
            { ull d = add2(Z.y, niz); db = fma2_(d, d, db);
              d = add2(W.y, niw);     db = fma2_(d, d, db); }
        }
        ull ta = mul2(da, K2), tb = mul2(db, K2);
        float t0, t1, t2, t3; up2(ta, t0, t1); up2(tb, t2, t3);
        ull wa = pk2(ex2f(t0), ex2f(t1));
        ull wb = pk2(ex2f(t2), ex2f(t3));
        S2a = add2(S2a, wa); T2a = fma2_(da, wa, T2a);
        S2b = add2(S2b, wb); T2b = fma2_(db, wb, T2b);
    }
    ull S2 = add2(S2a, S2b), T2 = add2(T2a, T2b);
    float s0, s1, u0, u1; up2(S2, s0, s1); up2(T2, u0, u1);
    sp[tid] = s0 + s1; tp[tid] = u0 + u1;
}

// ---------------- GEMM + epilogue into registers ---------------------------
// y[i,o] = sum_k x[i,k]*A[k,o] + s_i*sum_k x[i,k]*A[FP+k,o] + t_i*A[2FP,o]
//          + bias[o], then *m_i, BN, tanh
template <int FP>
__device__ __forceinline__ void gemm_epi(
    const float* x_s, const float* A_s, const float* s_s, const float* t_s,
    const float* m_s, const float* cn_s, int tid, float o[4][8])
{
    const int cs0 = (tid & 7) * 8;
    const int r0  = (tid >> 3) * 4;
    ull u[4][4], v[4][4];
#pragma unroll
    for (int r = 0; r < 4; r++)
#pragma unroll
        for (int c = 0; c < 4; c++) { u[r][c] = 0ull; v[r][c] = 0ull; }

    const float* xb = x_s + r0 * XS;
#pragma unroll 2
    for (int kq = 0; kq < FP / 4; kq++) {
        float xq[4][4];
#pragma unroll
        for (int r = 0; r < 4; r++)
            *reinterpret_cast<float4*>(xq[r]) =
                *reinterpret_cast<const float4*>(xb + r * XS + kq * 4);
#pragma unroll
        for (int j = 0; j < 4; j++) {
            const int k = kq * 4 + j;
            ulonglong2 a01 = *reinterpret_cast<const ulonglong2*>(&A_s[k * 64 + cs0]);
            ulonglong2 a23 = *reinterpret_cast<const ulonglong2*>(&A_s[k * 64 + cs0 + 4]);
            ulonglong2 q01 = *reinterpret_cast<const ulonglong2*>(&A_s[(FP + k) * 64 + cs0]);
            ulonglong2 q23 = *reinterpret_cast<const ulonglong2*>(&A_s[(FP + k) * 64 + cs0 + 4]);
#pragma unroll
            for (int r = 0; r < 4; r++) {
                ull xp = pk2(xq[r][j], xq[r][j]);
                u[r][0] = fma2_(xp, a01.x, u[r][0]);
                u[r][1] = fma2_(xp, a01.y, u[r][1]);
                u[r][2] = fma2_(xp, a23.x, u[r][2]);
                u[r][3] = fma2_(xp, a23.y, u[r][3]);
                v[r][0] = fma2_(xp, q01.x, v[r][0]);
                v[r][1] = fma2_(xp, q01.y, v[r][1]);
                v[r][2] = fma2_(xp, q23.x, v[r][2]);
                v[r][3] = fma2_(xp, q23.y, v[r][3]);
            }
        }
    }
#pragma unroll
    for (int r = 0; r < 4; r++) {
        const int i = r0 + r;
        const float s = s_s[i], t = t_s[i], m = m_s[i];
        const ull s2 = pk2(s, s);
#pragma unroll
        for (int c2 = 0; c2 < 4; c2++) {
            ull y2 = fma2_(s2, v[r][c2], u[r][c2]);
            float yl, yh; up2(y2, yl, yh);
            const int c = cs0 + c2 * 2;
            float a0 = (fmaf(t, A_s[2 * FP * 64 + c],     yl) + cn_s[c])     * m;
            float a1 = (fmaf(t, A_s[2 * FP * 64 + c + 1], yh) + cn_s[c + 1]) * m;
            o[r][c2 * 2]     = ftanh(fmaf(cn_s[64 + c],     a0, cn_s[128 + c]));
            o[r][c2 * 2 + 1] = ftanh(fmaf(cn_s[64 + c + 1], a1, cn_s[128 + c + 1]));
        }
    }
}

// ----------------------------------------------------------------------------
// Fused GNN: all 5 layers in one kernel. Cluster of 2 CTAs per batch; each CTA
// owns 256 rows resident in SMEM. Next layer's c (x cols 60-63) is pushed from
// epilogue registers into double-buffered SoA arrays, locally AND into the
// peer CTA via st.shared::cluster (ordered by one cluster barrier per layer).
// ----------------------------------------------------------------------------
__global__ __launch_bounds__(512, 1) __cluster_dims__(2, 1, 1)
void gnn_fused_kernel(
    const float* __restrict__ xx,
    const float* __restrict__ e1, const float* __restrict__ e2,
    const float* __restrict__ e3,
    const float* __restrict__ A0, const float* __restrict__ b0,
    const float* __restrict__ Ar, const float* __restrict__ br,
    const float* __restrict__ bng, const float* __restrict__ bnb)
{
    extern __shared__ float sm[];
    float* cbuf = sm;                  // 2 bufs x 4 coords x 512 = 4096
    float* x_s  = cbuf + 4096;         // 256*XS
    float* A_s  = x_s + 256 * XS;      // 129*64 max
    float* m_s  = A_s + 129 * 64;      // 256
    float* s_s  = m_s + 256;           // 256
    float* t_s  = s_s + 256;           // 256
    float* sp   = t_s + 256;           // 512
    float* tp   = sp + 512;            // 512
    float* cn_s = tp + 512;            // 192

    const int h   = blockIdx.x;        // rank in cluster (row half)
    const int ph  = 1 - h;             // peer rank
    const int b   = blockIdx.y;
    const int tid = threadIdx.x;
    const int cs0 = (tid & 7) * 8;
    const int r0  = (tid >> 3) * 4;
    const bool pusher = (cs0 == 56);   // owns output cols 56..63

    // coord array pointers: buf q, coord m -> cbuf + (q*4 + m)*512
    auto CX = [&](int q) { return cbuf + (q * 4 + 0) * 512; };
    auto CY = [&](int q) { return cbuf + (q * 4 + 1) * 512; };
    auto CZ = [&](int q) { return cbuf + (q * 4 + 2) * 512; };
    auto CW = [&](int q) { return cbuf + (q * 4 + 3) * 512; };

    // ---- init: mask, layer-0 features (FP=36, cols 33..35 zero), c buf0 ----
    if (tid < 256) {
        const float* r = xx + ((size_t)b * 512 + h * 256 + tid) * 30;
        m_s[tid] = r[0];
        int i1 = (int)fabsf(r[27]);
        int i2 = (int)fabsf(r[28]);
        int i3 = (int)fabsf(r[29]);
        float* xr = x_s + tid * XS;
        xr[0] = e1[2 * i1]; xr[1] = e1[2 * i1 + 1];
        xr[2] = e2[2 * i2]; xr[3] = e2[2 * i2 + 1];
        xr[4] = e3[2 * i3]; xr[5] = e3[2 * i3 + 1];
#pragma unroll
        for (int k = 0; k < 27; k++) xr[6 + k] = r[k];
        xr[33] = 0.f; xr[34] = 0.f; xr[35] = 0.f;
    }
    {   // layer-0 c (ND=2) for ALL 512 rows straight from xx
        const float* row = xx + ((size_t)b * 512 + tid) * 30;
        CX(0)[tid] = row[25];
        CY(0)[tid] = row[26];
    }
    // stage A0 padded to FP=36 (zero rows 33..35, 69..71; tail at 72)
    for (int idx = tid; idx < 73 * 64; idx += 512) {
        int kp = idx >> 6, c = idx & 63;
        float val = 0.f;
        if (kp < 33)                  val = A0[kp * 64 + c];
        else if (kp >= 36 && kp < 69) val = A0[(kp - 3) * 64 + c];
        else if (kp == 72)            val = A0[66 * 64 + c];
        A_s[idx] = val;
    }
    if (tid < 64) {
        cn_s[tid]       = b0[tid];
        cn_s[64 + tid]  = bng[tid] * ISRC;
        cn_s[128 + tid] = bnb[tid];
    }
    __syncthreads();

    // ---- layer 0 (reads c buf0, pushes c buf1) ----
    {
        pairwise_soa<2>(CX(0), CY(0), CZ(0), CW(0), sp, tp, tid, h);
        __syncthreads();
        if (tid < 256) {
            float m = m_s[tid];
            s_s[tid] = fmaf(m, sp[tid] + sp[tid + 256], -1.f);
            t_s[tid] = m * (tp[tid] + tp[tid + 256]);
        }
        __syncthreads();
        float o[4][8];
        gemm_epi<36>(x_s, A_s, s_s, t_s, m_s, cn_s, tid, o);
        if (pusher) {
#pragma unroll
            for (int r = 0; r < 4; r++) {
                int gi = h * 256 + r0 + r;
                CX(1)[gi] = o[r][4]; CY(1)[gi] = o[r][5];
                CZ(1)[gi] = o[r][6]; CW(1)[gi] = o[r][7];
                st_cluster_f32(mapa_(smem_u32(&CX(1)[gi]), ph), o[r][4]);
                st_cluster_f32(mapa_(smem_u32(&CY(1)[gi]), ph), o[r][5]);
                st_cluster_f32(mapa_(smem_u32(&CZ(1)[gi]), ph), o[r][6]);
                st_cluster_f32(mapa_(smem_u32(&CW(1)[gi]), ph), o[r][7]);
            }
        }
        __syncthreads();   // all x_s reads of this layer done
#pragma unroll
        for (int r = 0; r < 4; r++) {
            float4* dst = reinterpret_cast<float4*>(x_s + (r0 + r) * XS + cs0);
            dst[0] = make_float4(o[r][0], o[r][1], o[r][2], o[r][3]);
            dst[1] = make_float4(o[r][4], o[r][5], o[r][6], o[r][7]);
        }
        __syncthreads();   // new x visible
    }

    // ---- layers 1..4 (layer L=l+1 reads c buf L&1, pushes buf (L+1)&1) ----
#pragma unroll 1
    for (int l = 0; l < 4; l++) {
        const int rb = (l + 1) & 1;    // read buffer
        const int nb = l & 1;          // push buffer (= (l+2)&1)
        // stage layer weights (vectorized) + constants
        const float* A = Ar + l * 129 * 64;
        for (int idx = tid; idx < 2064; idx += 512)
            reinterpret_cast<float4*>(A_s)[idx] =
                reinterpret_cast<const float4*>(A)[idx];
        if (tid < 64) {
            cn_s[tid]       = br[l * 64 + tid];
            cn_s[64 + tid]  = bng[(l + 1) * 64 + tid] * ISRC;
            cn_s[128 + tid] = bnb[(l + 1) * 64 + tid];
        }
        cluster_sync_();   // peer's c pushes into buf rb complete & visible

        pairwise_soa<4>(CX(rb), CY(rb), CZ(rb), CW(rb), sp, tp, tid, h);
        __syncthreads();
        if (tid < 256) {
            float m = m_s[tid];
            s_s[tid] = fmaf(m, sp[tid] + sp[tid + 256], -1.f);
            t_s[tid] = m * (tp[tid] + tp[tid + 256]);
        }
        __syncthreads();

        float o[4][8];
        gemm_epi<64>(x_s, A_s, s_s, t_s, m_s, cn_s, tid, o);

        if (l < 3) {
            if (pusher) {
#pragma unroll
                for (int r = 0; r < 4; r++) {
                    int gi = h * 256 + r0 + r;
                    CX(nb)[gi] = o[r][4]; CY(nb)[gi] = o[r][5];
                    CZ(nb)[gi] = o[r][6]; CW(nb)[gi] = o[r][7];
                    st_cluster_f32(mapa_(smem_u32(&CX(nb)[gi]), ph), o[r][4]);
                    st_cluster_f32(mapa_(smem_u32(&CY(nb)[gi]), ph), o[r][5]);
                    st_cluster_f32(mapa_(smem_u32(&CZ(nb)[gi]), ph), o[r][6]);
                    st_cluster_f32(mapa_(smem_u32(&CW(nb)[gi]), ph), o[r][7]);
                }
            }
            __syncthreads();   // all x_s reads done before overwrite
#pragma unroll
            for (int r = 0; r < 4; r++) {
                float4* dst = reinterpret_cast<float4*>(x_s + (r0 + r) * XS + cs0);
                dst[0] = make_float4(o[r][0], o[r][1], o[r][2], o[r][3]);
                dst[1] = make_float4(o[r][4], o[r][5], o[r][6], o[r][7]);
            }
            __syncthreads();   // new x visible
        } else {
            // last layer: write straight to global for the dense head
#pragma unroll
            for (int r = 0; r < 4; r++) {
                float4* dst = reinterpret_cast<float4*>(
                    g_x0 + (size_t)b * 32768 + (h * 256 + r0 + r) * 64 + cs0);
                dst[0] = make_float4(o[r][0], o[r][1], o[r][2], o[r][3]);
                dst[1] = make_float4(o[r][4], o[r][5], o[r][6], o[r][7]);
            }
        }
    }
}

// ----------------------------------------------------------------------------
// Dense layer 0 split-K: 128 CTAs, each owns a K-chunk of 256. f32x2 packed.
// Deterministic: partials stored, reduced in finalize (no float atomics).
// ----------------------------------------------------------------------------
#define D0XS 257
__global__ __launch_bounds__(256, 1) void dense0_kernel(const float* __restrict__ W)
{
    extern __shared__ float sm[];
    float* Xs = sm;                 // 64 x 257 (padded)
    float* Ws = Xs + 64 * D0XS;     // 256 x 128
    const int tid = threadIdx.x;
    const int kc  = blockIdx.x;

    for (int idx = tid; idx < 64 * 256; idx += 256) {
        int bb = idx >> 8, k = idx & 255;
        Xs[bb * D0XS + k] = g_x0[(size_t)bb * 32768 + kc * 256 + k];
    }
    const float* wsrc = W + (size_t)kc * 256 * 128;
    for (int idx = tid; idx < 256 * 128 / 4; idx += 256)
        reinterpret_cast<float4*>(Ws)[idx] =
            reinterpret_cast<const float4*>(wsrc)[idx];
    __syncthreads();

    const int rg = tid >> 4;   // 0..15 -> rows rg*4..rg*4+3
    const int cg = tid & 15;   // 0..15 -> cols cg*8..cg*8+7
    ull acc[4][4];
#pragma unroll
    for (int r = 0; r < 4; r++)
#pragma unroll
        for (int c = 0; c < 4; c++) acc[r][c] = 0ull;

#pragma unroll 2
    for (int k = 0; k < 256; k++) {
        ulonglong2 w01 = *reinterpret_cast<const ulonglong2*>(&Ws[k * 128 + cg * 8]);
        ulonglong2 w23 = *reinterpret_cast<const ulonglong2*>(&Ws[k * 128 + cg * 8 + 4]);
#pragma unroll
        for (int r = 0; r < 4; r++) {
            float xv = Xs[(rg * 4 + r) * D0XS + k];
            ull xp = pk2(xv, xv);
            acc[r][0] = fma2_(xp, w01.x, acc[r][0]);
            acc[r][1] = fma2_(xp, w01.y, acc[r][1]);
            acc[r][2] = fma2_(xp, w23.x, acc[r][2]);
            acc[r][3] = fma2_(xp, w23.y, acc[r][3]);
        }
    }
    float* dst = g_part + (size_t)kc * 8192;
#pragma unroll
    for (int r = 0; r < 4; r++) {
        ulonglong2* d = reinterpret_cast<ulonglong2*>(&dst[(rg * 4 + r) * 128 + cg * 8]);
        d[0] = make_ulonglong2(acc[r][0], acc[r][1]);
        d[1] = make_ulonglong2(acc[r][2], acc[r][3]);
    }
}

// ----------------------------------------------------------------------------
// Finalize: reduce partials, BN+sigmoid, dense1, BN+sigmoid, W2, write (64,4)
// ----------------------------------------------------------------------------
__global__ __launch_bounds__(128, 1) void finalize_kernel(
    const float* __restrict__ db0, const float* __restrict__ dW1,
    const float* __restrict__ db1, const float* __restrict__ dbng,
    const float* __restrict__ dbnb, const float* __restrict__ W2,
    const float* __restrict__ b2, float* __restrict__ out)
{
    __shared__ float h0[128];
    __shared__ float h1[128];
    const int b = blockIdx.x;
    const int d = threadIdx.x;

    float a = db0[d];
#pragma unroll 4
    for (int kc = 0; kc < 128; kc++) a += g_part[(size_t)kc * 8192 + b * 128 + d];
    a = fmaf(dbng[d] * ISRC, a, dbnb[d]);
    h0[d] = 1.f / (1.f + __expf(-a));
    __syncthreads();

    float s = 0.f;
#pragma unroll 8
    for (int k = 0; k < 128; k++) s = fmaf(h0[k], dW1[k * 128 + d], s);
    s += db1[d];
    s = fmaf(dbng[128 + d] * ISRC, s, dbnb[128 + d]);
    h1[d] = 1.f / (1.f + __expf(-s));
    __syncthreads();

    if (d < 4) {
        float o = 0.f;
        if (d < 2) {
            o = b2[d];
            for (int k = 0; k < 128; k++) o = fmaf(h1[k], W2[k * 2 + d], o);
        }
        out[b * 4 + d] = o;
    }
}

// ----------------------------------------------------------------------------
extern "C" void kernel_launch(void* const* d_in, const int* in_sizes, int n_in,
                              void* d_out, int out_size)
{
    const float* xx   = (const float*)d_in[0];
    const float* emb1 = (const float*)d_in[1];
    const float* emb2 = (const float*)d_in[2];
    const float* emb3 = (const float*)d_in[3];
    const float* A0   = (const float*)d_in[4];
    const float* b0   = (const float*)d_in[5];
    const float* Ar   = (const float*)d_in[6];
    const float* br   = (const float*)d_in[7];
    const float* bng  = (const float*)d_in[8];
    const float* bnb  = (const float*)d_in[9];
    const float* dW0  = (const float*)d_in[10];
    const float* db0  = (const float*)d_in[11];
    const float* dW1  = (const float*)d_in[12];
    const float* db1  = (const float*)d_in[13];
    const float* dbng = (const float*)d_in[14];
    const float* dbnb = (const float*)d_in[15];
    const float* W2   = (const float*)d_in[16];
    const float* b2   = (const float*)d_in[17];
    float* out = (float*)d_out;

    const int G_SMEM  = (4096 + 256 * XS + 129 * 64 + 256 * 3 + 1024 + 192) * 4;
    const int D0_SMEM = (64 * D0XS + 256 * 128) * 4;

    cudaFuncSetAttribute(gnn_fused_kernel,
                         cudaFuncAttributeMaxDynamicSharedMemorySize, G_SMEM);
    cudaFuncSetAttribute(dense0_kernel,
                         cudaFuncAttributeMaxDynamicSharedMemorySize, D0_SMEM);

    dim3 grid(2, 64);
    gnn_fused_kernel<<<grid, 512, G_SMEM>>>(
        xx, emb1, emb2, emb3, A0, b0, Ar, br, bng, bnb);
    dense0_kernel<<<128, 256, D0_SMEM>>>(dW0);
    finalize_kernel<<<64, 128>>>(db0, dW1, db1, dbng, dbnb, W2, b2, out);
}